// round 3
// baseline (speedup 1.0000x reference)
#include <cuda_runtime.h>
#include <cub/cub.cuh>
#include <cstdint>

// Problem constants (B=4,H=8,S=1024,D=64)
#define BH 32
#define S 1024
#define D 64
#define N_ELE (BH * S * S)          // 33554432 = 2^25
#define SHIFT 12
#define NB (1u << (31 - SHIFT))     // 512K buckets

// Static device scratch (allocation-free rule: __device__ globals only)
__device__ float    g_score[N_ELE];      // signed cosine scores, row-major [BH*S, S]
__device__ unsigned g_hist[NB];          // bucket populations
__device__ unsigned g_cum[NB];           // exclusive scan of populations
__device__ float    g_wmag[NB];          // per-bucket weight magnitude
__device__ float    g_invq[BH * S];
__device__ float    g_invk[BH * S];
__device__ unsigned char g_scantemp[1u << 22];

// ---------------------------------------------------------------------------
// Stage 0: zero histogram (must be re-done every replay)
// ---------------------------------------------------------------------------
__global__ void zero_hist_kernel() {
    unsigned i = blockIdx.x * blockDim.x + threadIdx.x;
    uint4 z = make_uint4(0u, 0u, 0u, 0u);
    reinterpret_cast<uint4*>(g_hist)[i] = z;
}

// ---------------------------------------------------------------------------
// Stage 1: inverse lengths  inv = 1/(sqrt(sum sq)+1e-5), one warp per row
// ---------------------------------------------------------------------------
__global__ void norms_kernel(const float* __restrict__ q, const float* __restrict__ k) {
    int warp = (blockIdx.x * blockDim.x + threadIdx.x) >> 5;
    int lane = threadIdx.x & 31;
    if (warp >= 2 * BH * S) return;
    bool is_q = warp < BH * S;
    int row = is_q ? warp : warp - BH * S;
    const float* p = (is_q ? q : k) + (size_t)row * D;
    float v0 = p[lane], v1 = p[lane + 32];
    float s = v0 * v0 + v1 * v1;
    #pragma unroll
    for (int o = 16; o; o >>= 1) s += __shfl_xor_sync(0xffffffffu, s, o);
    if (lane == 0) (is_q ? g_invq : g_invk)[row] = 1.0f / (sqrtf(s) + 1e-5f);
}

// ---------------------------------------------------------------------------
// Stage 2: QK^T (fp32) -> signed scores (STG.128) + atomic bucket histogram
// 64x64 tile, 256 threads, 4x4 micro-tile, transposed smem (pitch 65)
// ---------------------------------------------------------------------------
__global__ void qk_kernel(const float* __restrict__ Q, const float* __restrict__ K) {
    __shared__ float Qs[64][65];   // Qs[d][r]
    __shared__ float Ks[64][65];   // Ks[d][c]
    int bh = blockIdx.z;
    int i0 = blockIdx.y * 64;
    int j0 = blockIdx.x * 64;
    const float* Qb = Q + ((size_t)bh * S + i0) * D;
    const float* Kb = K + ((size_t)bh * S + j0) * D;
    int tid = threadIdx.x;

    #pragma unroll
    for (int l = 0; l < 16; l++) {
        int idx = tid + l * 256;          // 0..4095
        int r = idx >> 6, d = idx & 63;
        Qs[d][r] = Qb[(size_t)r * D + d];
        Ks[d][r] = Kb[(size_t)r * D + d];
    }
    __syncthreads();

    int tx = tid & 15, ty = tid >> 4;
    float acc[4][4] = {};
    #pragma unroll 8
    for (int d = 0; d < 64; d++) {
        float a[4], b[4];
        #pragma unroll
        for (int u = 0; u < 4; u++) a[u] = Qs[d][ty * 4 + u];
        #pragma unroll
        for (int u = 0; u < 4; u++) b[u] = Ks[d][tx * 4 + u];
        #pragma unroll
        for (int r = 0; r < 4; r++)
            #pragma unroll
            for (int u = 0; u < 4; u++)
                acc[r][u] += a[r] * b[u];
    }

    float iq[4], ik[4];
    #pragma unroll
    for (int u = 0; u < 4; u++) {
        iq[u] = g_invq[bh * S + i0 + ty * 4 + u];
        ik[u] = g_invk[bh * S + j0 + tx * 4 + u];
    }
    #pragma unroll
    for (int r = 0; r < 4; r++) {
        unsigned row = (unsigned)(bh * S + i0 + ty * 4 + r);
        float s[4];
        #pragma unroll
        for (int u = 0; u < 4; u++) s[u] = acc[r][u] * iq[r] * ik[u];
        unsigned base = (row << 10) | (unsigned)(j0 + tx * 4);
        *reinterpret_cast<float4*>(&g_score[base]) =
            make_float4(s[0], s[1], s[2], s[3]);
        #pragma unroll
        for (int u = 0; u < 4; u++) {
            unsigned key = __float_as_uint(s[u]) & 0x7fffffffu;
            atomicAdd(&g_hist[key >> SHIFT], 1u);
        }
    }
}

// ---------------------------------------------------------------------------
// Stage 4: per-bucket weight magnitude:  wmag = -log(midrank/(n-1) + 1/n)
// ---------------------------------------------------------------------------
__global__ void wmag_kernel() {
    unsigned b = blockIdx.x * blockDim.x + threadIdx.x;
    unsigned pop = g_hist[b];
    if (pop == 0u) { g_wmag[b] = 0.0f; return; }
    float rmid = (float)g_cum[b] + 0.5f * (float)(pop - 1u);
    float prob = fmaf(rmid, 1.0f / (float)(N_ELE - 1), 0x1p-25f);
    g_wmag[b] = -logf(prob);
}

// ---------------------------------------------------------------------------
// Stage 5 (fused): out = (W / rowsum(|W|)) @ V, where W is materialized
// on-the-fly in the staging loop: w = sign(score) * wmag[bucket(|score|)]
// ---------------------------------------------------------------------------
__global__ void av_kernel(const float* __restrict__ V, float* __restrict__ out) {
    __shared__ float Ws[64][65];   // Ws[r][kk]
    __shared__ float Vs[64][65];   // Vs[kk][c]
    __shared__ float rsum[64];
    int bh = blockIdx.y;
    int i0 = blockIdx.x * 64;
    int tid = threadIdx.x, tx = tid & 15, ty = tid >> 4;
    const float* Wb = g_score + ((size_t)(bh * S + i0)) * S;
    const float* Vb = V + (size_t)bh * S * D;

    float acc[4][4] = {};
    float rs[4] = {};
    for (int kt = 0; kt < S; kt += 64) {
        #pragma unroll
        for (int l = 0; l < 16; l++) {
            int idx = tid + l * 256;
            int r = idx >> 6, c = idx & 63;
            float sc = Wb[(size_t)r * S + kt + c];
            unsigned key = __float_as_uint(sc) & 0x7fffffffu;
            float w = (key == 0u) ? 0.0f
                                  : copysignf(__ldg(&g_wmag[key >> SHIFT]), sc);
            Ws[r][c] = w;
            Vs[r][c] = Vb[(size_t)(kt + r) * D + c];
        }
        __syncthreads();
        #pragma unroll 8
        for (int kk = 0; kk < 64; kk++) {
            float a[4], b[4];
            #pragma unroll
            for (int u = 0; u < 4; u++) b[u] = Vs[kk][tx * 4 + u];
            #pragma unroll
            for (int r = 0; r < 4; r++) a[r] = Ws[ty * 4 + r][kk];
            if (tx == 0) {
                #pragma unroll
                for (int r = 0; r < 4; r++) rs[r] += fabsf(a[r]);
            }
            #pragma unroll
            for (int r = 0; r < 4; r++)
                #pragma unroll
                for (int u = 0; u < 4; u++)
                    acc[r][u] += a[r] * b[u];
        }
        __syncthreads();
    }
    if (tx == 0) {
        #pragma unroll
        for (int r = 0; r < 4; r++) rsum[ty * 4 + r] = rs[r];
    }
    __syncthreads();
    #pragma unroll
    for (int r = 0; r < 4; r++) {
        float inv = 1.0f / rsum[ty * 4 + r];
        size_t obase = ((size_t)(bh * S) + i0 + ty * 4 + r) * D + tx * 4;
        #pragma unroll
        for (int u = 0; u < 4; u++)
            out[obase + u] = acc[r][u] * inv;
    }
}

// ---------------------------------------------------------------------------
extern "C" void kernel_launch(void* const* d_in, const int* in_sizes, int n_in,
                              void* d_out, int out_size) {
    const float* q = (const float*)d_in[0];
    const float* k = (const float*)d_in[1];
    const float* v = (const float*)d_in[2];
    float* out = (float*)d_out;

    // Stage 0: zero histogram (512K words, uint4 stores)
    zero_hist_kernel<<<NB / 1024, 256>>>();

    // Stage 1: inverse lengths
    norms_kernel<<<8192, 256>>>(q, k);

    // Stage 2: cosine scores + bucket histogram
    dim3 g1(S / 64, S / 64, BH);
    qk_kernel<<<g1, 256>>>(q, k);

    // Stage 3: exclusive scan of bucket populations
    unsigned *hist_p, *cum_p;
    void* tmp;
    cudaGetSymbolAddress((void**)&hist_p, g_hist);
    cudaGetSymbolAddress((void**)&cum_p, g_cum);
    cudaGetSymbolAddress(&tmp, g_scantemp);
    size_t temp_bytes = 0;
    cub::DeviceScan::ExclusiveSum(nullptr, temp_bytes, hist_p, cum_p, (int)NB);
    if (temp_bytes > sizeof(g_scantemp)) return;
    cub::DeviceScan::ExclusiveSum(tmp, temp_bytes, hist_p, cum_p, (int)NB);

    // Stage 4: per-bucket weight magnitudes
    wmag_kernel<<<NB / 256, 256>>>();

    // Stage 5+6 fused: weights + row-L1-normalize + apply to V
    dim3 g2(S / 64, BH);
    av_kernel<<<g2, 256>>>(v, out);
}

// round 4
// speedup vs baseline: 1.0644x; 1.0644x over previous
#include <cuda_runtime.h>
#include <cub/cub.cuh>
#include <cstdint>

// Problem constants (B=4,H=8,S=1024,D=64)
#define BH 32
#define S 1024
#define D 64
#define N_ELE (BH * S * S)          // 33554432 = 2^25
#define SHIFT 12
#define NB (1u << (31 - SHIFT))     // 512K buckets
#define PITCH 68                    // 272B rows: float4-aligned smem

// Static device scratch (allocation-free rule: __device__ globals only)
__device__ float    g_score[N_ELE];      // signed cosine scores, row-major [BH*S, S]
__device__ float    g_w[N_ELE];          // final weights
__device__ unsigned g_hist[NB];          // bucket populations
__device__ unsigned g_cum[NB];           // exclusive scan of populations
__device__ float    g_wmag[NB];          // per-bucket weight magnitude
__device__ float    g_invq[BH * S];
__device__ float    g_invk[BH * S];
__device__ unsigned char g_scantemp[1u << 22];

// ---------------------------------------------------------------------------
// Stage 0: zero histogram (must be re-done every replay)
// ---------------------------------------------------------------------------
__global__ void zero_hist_kernel() {
    unsigned i = blockIdx.x * blockDim.x + threadIdx.x;
    reinterpret_cast<uint4*>(g_hist)[i] = make_uint4(0u, 0u, 0u, 0u);
}

// ---------------------------------------------------------------------------
// Stage 1: inverse lengths  inv = 1/(sqrt(sum sq)+1e-5), one warp per row
// ---------------------------------------------------------------------------
__global__ void norms_kernel(const float* __restrict__ q, const float* __restrict__ k) {
    int warp = (blockIdx.x * blockDim.x + threadIdx.x) >> 5;
    int lane = threadIdx.x & 31;
    if (warp >= 2 * BH * S) return;
    bool is_q = warp < BH * S;
    int row = is_q ? warp : warp - BH * S;
    const float* p = (is_q ? q : k) + (size_t)row * D;
    float v0 = p[lane], v1 = p[lane + 32];
    float s = v0 * v0 + v1 * v1;
    #pragma unroll
    for (int o = 16; o; o >>= 1) s += __shfl_xor_sync(0xffffffffu, s, o);
    if (lane == 0) (is_q ? g_invq : g_invk)[row] = 1.0f / (sqrtf(s) + 1e-5f);
}

// ---------------------------------------------------------------------------
// Stage 2: QK^T (fp32) -> signed scores (STG.128) + atomic bucket histogram
// 64x64 tile, 256 threads, 4x4 micro-tile, LDS.128 compute loads
// ---------------------------------------------------------------------------
__global__ void qk_kernel(const float* __restrict__ Q, const float* __restrict__ K) {
    __shared__ float Qs[64][PITCH];   // Qs[d][r]
    __shared__ float Ks[64][PITCH];   // Ks[d][c]
    int bh = blockIdx.z;
    int i0 = blockIdx.y * 64;
    int j0 = blockIdx.x * 64;
    const float* Qb = Q + ((size_t)bh * S + i0) * D;
    const float* Kb = K + ((size_t)bh * S + j0) * D;
    int tid = threadIdx.x;

    #pragma unroll
    for (int l = 0; l < 16; l++) {
        int idx = tid + l * 256;          // 0..4095
        int r = idx >> 6, d = idx & 63;
        Qs[d][r] = Qb[(size_t)r * D + d];
        Ks[d][r] = Kb[(size_t)r * D + d];
    }
    __syncthreads();

    int tx = tid & 15, ty = tid >> 4;
    float acc[4][4] = {};
    #pragma unroll 8
    for (int d = 0; d < 64; d++) {
        float4 a = *reinterpret_cast<const float4*>(&Qs[d][ty * 4]);
        float4 b = *reinterpret_cast<const float4*>(&Ks[d][tx * 4]);
        float av4[4] = {a.x, a.y, a.z, a.w};
        float bv4[4] = {b.x, b.y, b.z, b.w};
        #pragma unroll
        for (int r = 0; r < 4; r++)
            #pragma unroll
            for (int u = 0; u < 4; u++)
                acc[r][u] += av4[r] * bv4[u];
    }

    float iq[4], ik[4];
    #pragma unroll
    for (int u = 0; u < 4; u++) {
        iq[u] = g_invq[bh * S + i0 + ty * 4 + u];
        ik[u] = g_invk[bh * S + j0 + tx * 4 + u];
    }
    #pragma unroll
    for (int r = 0; r < 4; r++) {
        unsigned row = (unsigned)(bh * S + i0 + ty * 4 + r);
        float s[4];
        #pragma unroll
        for (int u = 0; u < 4; u++) s[u] = acc[r][u] * iq[r] * ik[u];
        unsigned base = (row << 10) | (unsigned)(j0 + tx * 4);
        *reinterpret_cast<float4*>(&g_score[base]) =
            make_float4(s[0], s[1], s[2], s[3]);
        #pragma unroll
        for (int u = 0; u < 4; u++) {
            unsigned key = __float_as_uint(s[u]) & 0x7fffffffu;
            atomicAdd(&g_hist[key >> SHIFT], 1u);
        }
    }
}

// ---------------------------------------------------------------------------
// Stage 4: per-bucket weight magnitude:  wmag = -log(midrank/(n-1) + 1/n)
// ---------------------------------------------------------------------------
__global__ void wmag_kernel() {
    unsigned b = blockIdx.x * blockDim.x + threadIdx.x;
    unsigned pop = g_hist[b];
    if (pop == 0u) { g_wmag[b] = 0.0f; return; }
    float rmid = (float)g_cum[b] + 0.5f * (float)(pop - 1u);
    float prob = fmaf(rmid, 1.0f / (float)(N_ELE - 1), 0x1p-25f);
    g_wmag[b] = -logf(prob);
}

// ---------------------------------------------------------------------------
// Stage 5: elementwise weights: w = sign(score) * wmag[bucket(|score|)]
// (streaming kernel: max MLP hides the random L2 gather)
// ---------------------------------------------------------------------------
__global__ void weight_kernel() {
    unsigned i = (blockIdx.x * blockDim.x + threadIdx.x) * 4u;
    float4 s4 = *reinterpret_cast<const float4*>(&g_score[i]);
    float sv[4] = {s4.x, s4.y, s4.z, s4.w};
    float w[4];
    #pragma unroll
    for (int u = 0; u < 4; u++) {
        unsigned key = __float_as_uint(sv[u]) & 0x7fffffffu;
        w[u] = (key == 0u) ? 0.0f : copysignf(__ldg(&g_wmag[key >> SHIFT]), sv[u]);
    }
    *reinterpret_cast<float4*>(&g_w[i]) = make_float4(w[0], w[1], w[2], w[3]);
}

// ---------------------------------------------------------------------------
// Stage 6: out = (W / rowsum(|W|)) @ V, fused (block owns full K=1024 rows)
// ---------------------------------------------------------------------------
__global__ void av_kernel(const float* __restrict__ V, float* __restrict__ out) {
    __shared__ float Ws[64][PITCH];   // Ws[r][kk]
    __shared__ float Vs[64][PITCH];   // Vs[kk][c]
    __shared__ float rsum[64];
    int bh = blockIdx.y;
    int i0 = blockIdx.x * 64;
    int tid = threadIdx.x, tx = tid & 15, ty = tid >> 4;
    const float* Wb = g_w + ((size_t)(bh * S + i0)) * S;
    const float* Vb = V + (size_t)bh * S * D;

    float acc[4][4] = {};
    float rs[4] = {};
    for (int kt = 0; kt < S; kt += 64) {
        #pragma unroll
        for (int l = 0; l < 16; l++) {
            int idx = tid + l * 256;
            int r = idx >> 6, c = idx & 63;
            Ws[r][c] = Wb[(size_t)r * S + kt + c];
            Vs[r][c] = Vb[(size_t)(kt + r) * D + c];
        }
        __syncthreads();
        #pragma unroll 8
        for (int kk = 0; kk < 64; kk++) {
            float4 b = *reinterpret_cast<const float4*>(&Vs[kk][tx * 4]);
            float bv4[4] = {b.x, b.y, b.z, b.w};
            float a[4];
            #pragma unroll
            for (int r = 0; r < 4; r++) a[r] = Ws[ty * 4 + r][kk];
            if (tx == 0) {
                #pragma unroll
                for (int r = 0; r < 4; r++) rs[r] += fabsf(a[r]);
            }
            #pragma unroll
            for (int r = 0; r < 4; r++)
                #pragma unroll
                for (int u = 0; u < 4; u++)
                    acc[r][u] += a[r] * bv4[u];
        }
        __syncthreads();
    }
    if (tx == 0) {
        #pragma unroll
        for (int r = 0; r < 4; r++) rsum[ty * 4 + r] = rs[r];
    }
    __syncthreads();
    #pragma unroll
    for (int r = 0; r < 4; r++) {
        float inv = 1.0f / rsum[ty * 4 + r];
        size_t obase = ((size_t)(bh * S) + i0 + ty * 4 + r) * D + tx * 4;
        #pragma unroll
        for (int u = 0; u < 4; u++)
            out[obase + u] = acc[r][u] * inv;
    }
}

// ---------------------------------------------------------------------------
extern "C" void kernel_launch(void* const* d_in, const int* in_sizes, int n_in,
                              void* d_out, int out_size) {
    const float* q = (const float*)d_in[0];
    const float* k = (const float*)d_in[1];
    const float* v = (const float*)d_in[2];
    float* out = (float*)d_out;

    // Stage 0: zero histogram (512K words, uint4 stores)
    zero_hist_kernel<<<NB / 1024, 256>>>();

    // Stage 1: inverse lengths
    norms_kernel<<<8192, 256>>>(q, k);

    // Stage 2: cosine scores + bucket histogram
    dim3 g1(S / 64, S / 64, BH);
    qk_kernel<<<g1, 256>>>(q, k);

    // Stage 3: exclusive scan of bucket populations
    unsigned *hist_p, *cum_p;
    void* tmp;
    cudaGetSymbolAddress((void**)&hist_p, g_hist);
    cudaGetSymbolAddress((void**)&cum_p, g_cum);
    cudaGetSymbolAddress(&tmp, g_scantemp);
    size_t temp_bytes = 0;
    cub::DeviceScan::ExclusiveSum(nullptr, temp_bytes, hist_p, cum_p, (int)NB);
    if (temp_bytes > sizeof(g_scantemp)) return;
    cub::DeviceScan::ExclusiveSum(tmp, temp_bytes, hist_p, cum_p, (int)NB);

    // Stage 4: per-bucket weight magnitudes
    wmag_kernel<<<NB / 256, 256>>>();

    // Stage 5: elementwise weights (streaming, high MLP)
    weight_kernel<<<N_ELE / 1024, 256>>>();

    // Stage 6: row-L1-normalize + apply to V
    dim3 g2(S / 64, BH);
    av_kernel<<<g2, 256>>>(v, out);
}

// round 5
// speedup vs baseline: 1.1110x; 1.0437x over previous
#include <cuda_runtime.h>
#include <cub/cub.cuh>
#include <cstdint>

// Problem constants (B=4,H=8,S=1024,D=64)
#define BH 32
#define S 1024
#define D 64
#define N_ELE (BH * S * S)          // 33554432 = 2^25
#define SHIFT 9
#define NB (1u << (31 - SHIFT))     // 4M buckets
#define QPITCH 129                  // 128-wide tile pitch (mod 32 == 1)

// Static device scratch (allocation-free rule: __device__ globals only)
__device__ float    g_score[N_ELE];      // signed cosine scores, row-major [BH*S, S]
__device__ float    g_w[N_ELE];          // final weights
__device__ unsigned g_hist[NB];          // bucket populations
__device__ unsigned g_cum[NB];           // exclusive scan of populations
__device__ float    g_wmag[NB];          // per-bucket weight magnitude
__device__ float    g_invq[BH * S];
__device__ float    g_invk[BH * S];
__device__ unsigned char g_scantemp[1u << 22];

// ---------------------------------------------------------------------------
// Stage 0: zero histogram (must be re-done every replay)
// ---------------------------------------------------------------------------
__global__ void zero_hist_kernel() {
    unsigned i = blockIdx.x * blockDim.x + threadIdx.x;
    reinterpret_cast<uint4*>(g_hist)[i] = make_uint4(0u, 0u, 0u, 0u);
}

// ---------------------------------------------------------------------------
// Stage 1: inverse lengths  inv = 1/(sqrt(sum sq)+1e-5), one warp per row
// ---------------------------------------------------------------------------
__global__ void norms_kernel(const float* __restrict__ q, const float* __restrict__ k) {
    int warp = (blockIdx.x * blockDim.x + threadIdx.x) >> 5;
    int lane = threadIdx.x & 31;
    if (warp >= 2 * BH * S) return;
    bool is_q = warp < BH * S;
    int row = is_q ? warp : warp - BH * S;
    const float* p = (is_q ? q : k) + (size_t)row * D;
    float v0 = p[lane], v1 = p[lane + 32];
    float s = v0 * v0 + v1 * v1;
    #pragma unroll
    for (int o = 16; o; o >>= 1) s += __shfl_xor_sync(0xffffffffu, s, o);
    if (lane == 0) (is_q ? g_invq : g_invk)[row] = 1.0f / (sqrtf(s) + 1e-5f);
}

// ---------------------------------------------------------------------------
// Stage 2: QK^T (fp32) -> signed scores (STG.128) + atomic bucket histogram
// 128x128 tile, 256 threads, 8x8 micro-tile (FFMA-bound), dynamic smem
// ---------------------------------------------------------------------------
__global__ void qk_kernel(const float* __restrict__ Q, const float* __restrict__ K) {
    extern __shared__ float sm[];
    float* Qs = sm;                    // [64][QPITCH]  Qs[d][r]
    float* Ks = sm + 64 * QPITCH;      // [64][QPITCH]  Ks[d][c]
    int bh = blockIdx.z;
    int i0 = blockIdx.y * 128;
    int j0 = blockIdx.x * 128;
    const float* Qb = Q + ((size_t)bh * S + i0) * D;
    const float* Kb = K + ((size_t)bh * S + j0) * D;
    int tid = threadIdx.x;

    #pragma unroll
    for (int l = 0; l < 32; l++) {
        int idx = tid + l * 256;          // 0..8191
        int r = idx >> 6, d = idx & 63;   // consecutive threads vary d: STS stride QPITCH (conflict-free)
        Qs[d * QPITCH + r] = Qb[(size_t)r * D + d];
        Ks[d * QPITCH + r] = Kb[(size_t)r * D + d];
    }
    __syncthreads();

    int tx = tid & 15, ty = tid >> 4;     // 16x16 threads, 8x8 each
    float acc[8][8] = {};
    #pragma unroll 8
    for (int d = 0; d < 64; d++) {
        float a[8], b[8];
        const float* Qrow = &Qs[d * QPITCH + ty * 8];
        const float* Krow = &Ks[d * QPITCH + tx * 8];
        #pragma unroll
        for (int u = 0; u < 8; u++) a[u] = Qrow[u];
        #pragma unroll
        for (int u = 0; u < 8; u++) b[u] = Krow[u];
        #pragma unroll
        for (int r = 0; r < 8; r++)
            #pragma unroll
            for (int u = 0; u < 8; u++)
                acc[r][u] += a[r] * b[u];
    }

    float iq[8], ik[8];
    #pragma unroll
    for (int u = 0; u < 8; u++) {
        iq[u] = g_invq[bh * S + i0 + ty * 8 + u];
        ik[u] = g_invk[bh * S + j0 + tx * 8 + u];
    }
    #pragma unroll
    for (int r = 0; r < 8; r++) {
        unsigned row = (unsigned)(bh * S + i0 + ty * 8 + r);
        float s[8];
        #pragma unroll
        for (int u = 0; u < 8; u++) s[u] = acc[r][u] * iq[r] * ik[u];
        unsigned base = (row << 10) | (unsigned)(j0 + tx * 8);
        *reinterpret_cast<float4*>(&g_score[base]) =
            make_float4(s[0], s[1], s[2], s[3]);
        *reinterpret_cast<float4*>(&g_score[base + 4]) =
            make_float4(s[4], s[5], s[6], s[7]);
        #pragma unroll
        for (int u = 0; u < 8; u++) {
            unsigned key = __float_as_uint(s[u]) & 0x7fffffffu;
            atomicAdd(&g_hist[key >> SHIFT], 1u);
        }
    }
}

// ---------------------------------------------------------------------------
// Stage 4: per-bucket weight magnitude:  wmag = -log(midrank/(n-1) + 1/n)
// ---------------------------------------------------------------------------
__global__ void wmag_kernel() {
    unsigned b = blockIdx.x * blockDim.x + threadIdx.x;
    unsigned pop = g_hist[b];
    if (pop == 0u) { g_wmag[b] = 0.0f; return; }
    float rmid = (float)g_cum[b] + 0.5f * (float)(pop - 1u);
    float prob = fmaf(rmid, 1.0f / (float)(N_ELE - 1), 0x1p-25f);
    g_wmag[b] = -logf(prob);
}

// ---------------------------------------------------------------------------
// Stage 5: elementwise weights: w = sign(score) * wmag[bucket(|score|)]
// (streaming kernel: max MLP hides the random L2 gather)
// ---------------------------------------------------------------------------
__global__ void weight_kernel() {
    unsigned i = (blockIdx.x * blockDim.x + threadIdx.x) * 4u;
    float4 s4 = *reinterpret_cast<const float4*>(&g_score[i]);
    float sv[4] = {s4.x, s4.y, s4.z, s4.w};
    float w[4];
    #pragma unroll
    for (int u = 0; u < 4; u++) {
        unsigned key = __float_as_uint(sv[u]) & 0x7fffffffu;
        w[u] = (key == 0u) ? 0.0f : copysignf(__ldg(&g_wmag[key >> SHIFT]), sv[u]);
    }
    *reinterpret_cast<float4*>(&g_w[i]) = make_float4(w[0], w[1], w[2], w[3]);
}

// ---------------------------------------------------------------------------
// Stage 6: out = (W / rowsum(|W|)) @ V, fused (block owns full K=1024 rows)
// (unchanged from the proven 634us configuration)
// ---------------------------------------------------------------------------
__global__ void av_kernel(const float* __restrict__ V, float* __restrict__ out) {
    __shared__ float Ws[64][65];   // Ws[r][kk]
    __shared__ float Vs[64][65];   // Vs[kk][c]
    __shared__ float rsum[64];
    int bh = blockIdx.y;
    int i0 = blockIdx.x * 64;
    int tid = threadIdx.x, tx = tid & 15, ty = tid >> 4;
    const float* Wb = g_w + ((size_t)(bh * S + i0)) * S;
    const float* Vb = V + (size_t)bh * S * D;

    float acc[4][4] = {};
    float rs[4] = {};
    for (int kt = 0; kt < S; kt += 64) {
        #pragma unroll
        for (int l = 0; l < 16; l++) {
            int idx = tid + l * 256;
            int r = idx >> 6, c = idx & 63;
            Ws[r][c] = Wb[(size_t)r * S + kt + c];
            Vs[r][c] = Vb[(size_t)(kt + r) * D + c];
        }
        __syncthreads();
        #pragma unroll 8
        for (int kk = 0; kk < 64; kk++) {
            float a[4], b[4];
            #pragma unroll
            for (int u = 0; u < 4; u++) b[u] = Vs[kk][tx * 4 + u];
            #pragma unroll
            for (int r = 0; r < 4; r++) a[r] = Ws[ty * 4 + r][kk];
            if (tx == 0) {
                #pragma unroll
                for (int r = 0; r < 4; r++) rs[r] += fabsf(a[r]);
            }
            #pragma unroll
            for (int r = 0; r < 4; r++)
                #pragma unroll
                for (int u = 0; u < 4; u++)
                    acc[r][u] += a[r] * b[u];
        }
        __syncthreads();
    }
    if (tx == 0) {
        #pragma unroll
        for (int r = 0; r < 4; r++) rsum[ty * 4 + r] = rs[r];
    }
    __syncthreads();
    #pragma unroll
    for (int r = 0; r < 4; r++) {
        float inv = 1.0f / rsum[ty * 4 + r];
        size_t obase = ((size_t)(bh * S) + i0 + ty * 4 + r) * D + tx * 4;
        #pragma unroll
        for (int u = 0; u < 4; u++)
            out[obase + u] = acc[r][u] * inv;
    }
}

// ---------------------------------------------------------------------------
extern "C" void kernel_launch(void* const* d_in, const int* in_sizes, int n_in,
                              void* d_out, int out_size) {
    const float* q = (const float*)d_in[0];
    const float* k = (const float*)d_in[1];
    const float* v = (const float*)d_in[2];
    float* out = (float*)d_out;

    // Stage 0: zero histogram (4M words, uint4 stores)
    zero_hist_kernel<<<NB / 1024, 256>>>();

    // Stage 1: inverse lengths
    norms_kernel<<<8192, 256>>>(q, k);

    // Stage 2: cosine scores + bucket histogram (128x128 tiles, 66KB dyn smem)
    const int qk_smem = 2 * 64 * QPITCH * sizeof(float);
    cudaFuncSetAttribute(qk_kernel, cudaFuncAttributeMaxDynamicSharedMemorySize,
                         qk_smem);
    dim3 g1(S / 128, S / 128, BH);
    qk_kernel<<<g1, 256, qk_smem>>>(q, k);

    // Stage 3: exclusive scan of bucket populations
    unsigned *hist_p, *cum_p;
    void* tmp;
    cudaGetSymbolAddress((void**)&hist_p, g_hist);
    cudaGetSymbolAddress((void**)&cum_p, g_cum);
    cudaGetSymbolAddress(&tmp, g_scantemp);
    size_t temp_bytes = 0;
    cub::DeviceScan::ExclusiveSum(nullptr, temp_bytes, hist_p, cum_p, (int)NB);
    if (temp_bytes > sizeof(g_scantemp)) return;
    cub::DeviceScan::ExclusiveSum(tmp, temp_bytes, hist_p, cum_p, (int)NB);

    // Stage 4: per-bucket weight magnitudes
    wmag_kernel<<<NB / 256, 256>>>();

    // Stage 5: elementwise weights (streaming, high MLP)
    weight_kernel<<<N_ELE / 1024, 256>>>();

    // Stage 6: row-L1-normalize + apply to V
    dim3 g2(S / 64, BH);
    av_kernel<<<g2, 256>>>(v, out);
}

// round 6
// speedup vs baseline: 1.5589x; 1.4032x over previous
#include <cuda_runtime.h>
#include <cub/cub.cuh>
#include <cstdint>

// Problem constants (B=4,H=8,S=1024,D=64)
#define BH 32
#define S 1024
#define D 64
#define N_ELE (BH * S * S)          // 33554432 = 2^25
#define SHIFT 9
#define NB (1u << (31 - SHIFT))     // 4M buckets
#define QPITCH 129                  // 128-wide tile pitch (mod 32 == 1)

// Static device scratch (allocation-free rule: __device__ globals only)
__device__ float    g_score[N_ELE];      // signed cosine scores, row-major [BH*S, S]
__device__ float    g_w[N_ELE];          // final weights
__device__ unsigned g_hist[NB];          // bucket populations
__device__ unsigned g_cum[NB];           // exclusive scan of populations
__device__ float    g_wmag[NB];          // per-bucket weight magnitude
__device__ float    g_invq[BH * S];
__device__ float    g_invk[BH * S];
__device__ unsigned char g_scantemp[1u << 22];

// ---------------------------------------------------------------------------
// Stage 0: zero histogram (must be re-done every replay)
// ---------------------------------------------------------------------------
__global__ void zero_hist_kernel() {
    unsigned i = blockIdx.x * blockDim.x + threadIdx.x;
    reinterpret_cast<uint4*>(g_hist)[i] = make_uint4(0u, 0u, 0u, 0u);
}

// ---------------------------------------------------------------------------
// Stage 1: inverse lengths  inv = 1/(sqrt(sum sq)+1e-5), one warp per row
// ---------------------------------------------------------------------------
__global__ void norms_kernel(const float* __restrict__ q, const float* __restrict__ k) {
    int warp = (blockIdx.x * blockDim.x + threadIdx.x) >> 5;
    int lane = threadIdx.x & 31;
    if (warp >= 2 * BH * S) return;
    bool is_q = warp < BH * S;
    int row = is_q ? warp : warp - BH * S;
    const float* p = (is_q ? q : k) + (size_t)row * D;
    float v0 = p[lane], v1 = p[lane + 32];
    float s = v0 * v0 + v1 * v1;
    #pragma unroll
    for (int o = 16; o; o >>= 1) s += __shfl_xor_sync(0xffffffffu, s, o);
    if (lane == 0) (is_q ? g_invq : g_invk)[row] = 1.0f / (sqrtf(s) + 1e-5f);
}

// ---------------------------------------------------------------------------
// Stage 2: QK^T (fp32) -> signed scores (STG.128) + atomic bucket histogram
// 128x128 tile, 256 threads, 8x8 micro-tile (FFMA-bound), dynamic smem
// ---------------------------------------------------------------------------
__global__ void qk_kernel(const float* __restrict__ Q, const float* __restrict__ K) {
    extern __shared__ float sm[];
    float* Qs = sm;                    // [64][QPITCH]  Qs[d][r]
    float* Ks = sm + 64 * QPITCH;      // [64][QPITCH]  Ks[d][c]
    int bh = blockIdx.z;
    int i0 = blockIdx.y * 128;
    int j0 = blockIdx.x * 128;
    const float* Qb = Q + ((size_t)bh * S + i0) * D;
    const float* Kb = K + ((size_t)bh * S + j0) * D;
    int tid = threadIdx.x;

    #pragma unroll
    for (int l = 0; l < 32; l++) {
        int idx = tid + l * 256;          // 0..8191
        int r = idx >> 6, d = idx & 63;   // consecutive threads vary d: STS stride QPITCH (conflict-free)
        Qs[d * QPITCH + r] = Qb[(size_t)r * D + d];
        Ks[d * QPITCH + r] = Kb[(size_t)r * D + d];
    }
    __syncthreads();

    int tx = tid & 15, ty = tid >> 4;     // 16x16 threads, 8x8 each
    float acc[8][8] = {};
    #pragma unroll 8
    for (int d = 0; d < 64; d++) {
        float a[8], b[8];
        const float* Qrow = &Qs[d * QPITCH + ty * 8];
        const float* Krow = &Ks[d * QPITCH + tx * 8];
        #pragma unroll
        for (int u = 0; u < 8; u++) a[u] = Qrow[u];
        #pragma unroll
        for (int u = 0; u < 8; u++) b[u] = Krow[u];
        #pragma unroll
        for (int r = 0; r < 8; r++)
            #pragma unroll
            for (int u = 0; u < 8; u++)
                acc[r][u] += a[r] * b[u];
    }

    float iq[8], ik[8];
    #pragma unroll
    for (int u = 0; u < 8; u++) {
        iq[u] = g_invq[bh * S + i0 + ty * 8 + u];
        ik[u] = g_invk[bh * S + j0 + tx * 8 + u];
    }
    #pragma unroll
    for (int r = 0; r < 8; r++) {
        unsigned row = (unsigned)(bh * S + i0 + ty * 8 + r);
        float s[8];
        #pragma unroll
        for (int u = 0; u < 8; u++) s[u] = acc[r][u] * iq[r] * ik[u];
        unsigned base = (row << 10) | (unsigned)(j0 + tx * 8);
        *reinterpret_cast<float4*>(&g_score[base]) =
            make_float4(s[0], s[1], s[2], s[3]);
        *reinterpret_cast<float4*>(&g_score[base + 4]) =
            make_float4(s[4], s[5], s[6], s[7]);
        #pragma unroll
        for (int u = 0; u < 8; u++) {
            unsigned key = __float_as_uint(s[u]) & 0x7fffffffu;
            atomicAdd(&g_hist[key >> SHIFT], 1u);
        }
    }
}

// ---------------------------------------------------------------------------
// Stage 4: per-bucket weight magnitude:  wmag = -log(midrank/(n-1) + 1/n)
// ---------------------------------------------------------------------------
__global__ void wmag_kernel() {
    unsigned b = blockIdx.x * blockDim.x + threadIdx.x;
    unsigned pop = g_hist[b];
    if (pop == 0u) { g_wmag[b] = 0.0f; return; }
    float rmid = (float)g_cum[b] + 0.5f * (float)(pop - 1u);
    float prob = fmaf(rmid, 1.0f / (float)(N_ELE - 1), 0x1p-25f);
    g_wmag[b] = -logf(prob);
}

// ---------------------------------------------------------------------------
// Stage 5: elementwise weights: w = sign(score) * wmag[bucket(|score|)]
// (streaming kernel: max MLP hides the random L2 gather)
// ---------------------------------------------------------------------------
__global__ void weight_kernel() {
    unsigned i = (blockIdx.x * blockDim.x + threadIdx.x) * 4u;
    float4 s4 = *reinterpret_cast<const float4*>(&g_score[i]);
    float sv[4] = {s4.x, s4.y, s4.z, s4.w};
    float w[4];
    #pragma unroll
    for (int u = 0; u < 4; u++) {
        unsigned key = __float_as_uint(sv[u]) & 0x7fffffffu;
        w[u] = (key == 0u) ? 0.0f : copysignf(__ldg(&g_wmag[key >> SHIFT]), sv[u]);
    }
    *reinterpret_cast<float4*>(&g_w[i]) = make_float4(w[0], w[1], w[2], w[3]);
}

// ---------------------------------------------------------------------------
// Stage 6: out = (W / rowsum(|W|)) @ V, fused (block owns full K=1024 rows)
// (unchanged from the proven 634us configuration)
// ---------------------------------------------------------------------------
__global__ void av_kernel(const float* __restrict__ V, float* __restrict__ out) {
    __shared__ float Ws[64][65];   // Ws[r][kk]
    __shared__ float Vs[64][65];   // Vs[kk][c]
    __shared__ float rsum[64];
    int bh = blockIdx.y;
    int i0 = blockIdx.x * 64;
    int tid = threadIdx.x, tx = tid & 15, ty = tid >> 4;
    const float* Wb = g_w + ((size_t)(bh * S + i0)) * S;
    const float* Vb = V + (size_t)bh * S * D;

    float acc[4][4] = {};
    float rs[4] = {};
    for (int kt = 0; kt < S; kt += 64) {
        #pragma unroll
        for (int l = 0; l < 16; l++) {
            int idx = tid + l * 256;
            int r = idx >> 6, c = idx & 63;
            Ws[r][c] = Wb[(size_t)r * S + kt + c];
            Vs[r][c] = Vb[(size_t)(kt + r) * D + c];
        }
        __syncthreads();
        #pragma unroll 8
        for (int kk = 0; kk < 64; kk++) {
            float a[4], b[4];
            #pragma unroll
            for (int u = 0; u < 4; u++) b[u] = Vs[kk][tx * 4 + u];
            #pragma unroll
            for (int r = 0; r < 4; r++) a[r] = Ws[ty * 4 + r][kk];
            if (tx == 0) {
                #pragma unroll
                for (int r = 0; r < 4; r++) rs[r] += fabsf(a[r]);
            }
            #pragma unroll
            for (int r = 0; r < 4; r++)
                #pragma unroll
                for (int u = 0; u < 4; u++)
                    acc[r][u] += a[r] * b[u];
        }
        __syncthreads();
    }
    if (tx == 0) {
        #pragma unroll
        for (int r = 0; r < 4; r++) rsum[ty * 4 + r] = rs[r];
    }
    __syncthreads();
    #pragma unroll
    for (int r = 0; r < 4; r++) {
        float inv = 1.0f / rsum[ty * 4 + r];
        size_t obase = ((size_t)(bh * S) + i0 + ty * 4 + r) * D + tx * 4;
        #pragma unroll
        for (int u = 0; u < 4; u++)
            out[obase + u] = acc[r][u] * inv;
    }
}

// ---------------------------------------------------------------------------
extern "C" void kernel_launch(void* const* d_in, const int* in_sizes, int n_in,
                              void* d_out, int out_size) {
    const float* q = (const float*)d_in[0];
    const float* k = (const float*)d_in[1];
    const float* v = (const float*)d_in[2];
    float* out = (float*)d_out;

    // Stage 0: zero histogram (4M words, uint4 stores)
    zero_hist_kernel<<<NB / 1024, 256>>>();

    // Stage 1: inverse lengths
    norms_kernel<<<8192, 256>>>(q, k);

    // Stage 2: cosine scores + bucket histogram (128x128 tiles, 66KB dyn smem)
    const int qk_smem = 2 * 64 * QPITCH * sizeof(float);
    cudaFuncSetAttribute(qk_kernel, cudaFuncAttributeMaxDynamicSharedMemorySize,
                         qk_smem);
    dim3 g1(S / 128, S / 128, BH);
    qk_kernel<<<g1, 256, qk_smem>>>(q, k);

    // Stage 3: exclusive scan of bucket populations
    unsigned *hist_p, *cum_p;
    void* tmp;
    cudaGetSymbolAddress((void**)&hist_p, g_hist);
    cudaGetSymbolAddress((void**)&cum_p, g_cum);
    cudaGetSymbolAddress(&tmp, g_scantemp);
    size_t temp_bytes = 0;
    cub::DeviceScan::ExclusiveSum(nullptr, temp_bytes, hist_p, cum_p, (int)NB);
    if (temp_bytes > sizeof(g_scantemp)) return;
    cub::DeviceScan::ExclusiveSum(tmp, temp_bytes, hist_p, cum_p, (int)NB);

    // Stage 4: per-bucket weight magnitudes
    wmag_kernel<<<NB / 256, 256>>>();

    // Stage 5: elementwise weights (streaming, high MLP)
    weight_kernel<<<N_ELE / 1024, 256>>>();

    // Stage 6: row-L1-normalize + apply to V
    dim3 g2(S / 64, BH);
    av_kernel<<<g2, 256>>>(v, out);
}